// round 15
// baseline (speedup 1.0000x reference)
#include <cuda_runtime.h>

// Fixed shapes: B=16, H=W=1536
#define H_DIM  1536
#define W_DIM  1536
#define B_DIM  16
#define HW     (H_DIM * W_DIM)      // 2359296
#define HW4    (HW / 4)             // 589824 float4 per plane
#define W4     (W_DIM / 4)          // 384 float4 per row

// 36-bit tile masks, bit index = (r%6)*6 + (c%6)
#define R_MASK ((1ull<<4)|(1ull<<6)|(1ull<<8)|(1ull<<16)|(1ull<<19)|(1ull<<27)|(1ull<<29)|(1ull<<31))
#define B_MASK ((1ull<<1)|(1ull<<9)|(1ull<<11)|(1ull<<13)|(1ull<<22)|(1ull<<24)|(1ull<<26)|(1ull<<34))

// Plane-specialized: grid.z selects output channel; each CTA touches only
// 2-3 DRAM streams (vs 8 in the fused version). Traffic is identical.
__global__ __launch_bounds__(W4, 4) void xflat_rgb_extract_kernel(
    const float4* __restrict__ green,   // [B,1,H,W]
    const float4* __restrict__ xtrans,  // [B,3,H,W]
    const float4* __restrict__ chroma,  // [B,2,H,W]
    float4* __restrict__ out)           // [B,3,H,W]
{
    const int w4 = threadIdx.x;        // 0..383
    const int h  = blockIdx.x;         // 0..1535
    const int b  = blockIdx.y;         // 0..15
    const int z  = blockIdx.z;         // 0..2: output channel

    const int rowOff = h * W4 + w4;    // float4 units
    const int b3 = b * (3 * HW4);      // xtrans / out base

    if (z == 1) {
        // ch1: straight copy of green plane
        out[b3 + HW4 + rowOff] = green[b * HW4 + rowOff];
        return;
    }

    // Row mask pattern for this channel: 6 bits, doubled to 12
    const int r6 = h % 6;
    const unsigned long long M = (z == 0) ? R_MASK : B_MASK;
    unsigned m = (unsigned)((M >> (r6 * 6)) & 63u);
    m |= m << 6;

    const int c0 = (w4 * 4) % 6;       // column residue of lane 0
    const int b2 = b * (2 * HW4);      // chroma base

    // z==0: xtrans plane 0 vs chroma plane 0 -> out plane 0
    // z==2: xtrans plane 2 vs chroma plane 1 -> out plane 2
    const int xPlane = (z == 0) ? 0 : 2;
    const int cPlane = (z == 0) ? 0 : 1;

    const float4 xv = xtrans[b3 + xPlane * HW4 + rowOff];
    const float4 cv = chroma[b2 + cPlane * HW4 + rowOff];

    float4 o;
    o.x = ((m >> (c0 + 0)) & 1u) ? xv.x : cv.x;
    o.y = ((m >> (c0 + 1)) & 1u) ? xv.y : cv.y;
    o.z = ((m >> (c0 + 2)) & 1u) ? xv.z : cv.z;
    o.w = ((m >> (c0 + 3)) & 1u) ? xv.w : cv.w;

    out[b3 + xPlane * HW4 + rowOff] = o;
}

extern "C" void kernel_launch(void* const* d_in, const int* in_sizes, int n_in,
                              void* d_out, int out_size)
{
    const float4* green  = (const float4*)d_in[0];  // green_pred  [16,1,1536,1536]
    const float4* xtrans = (const float4*)d_in[1];  // xtrans      [16,3,1536,1536]
    const float4* chroma = (const float4*)d_in[2];  // chroma_pred [16,2,1536,1536]
    float4* out = (float4*)d_out;                   // [16,3,1536,1536] float32

    dim3 grid(H_DIM, B_DIM, 3);
    dim3 block(W4);
    xflat_rgb_extract_kernel<<<grid, block>>>(green, xtrans, chroma, out);
}

// round 16
// speedup vs baseline: 1.0382x; 1.0382x over previous
#include <cuda_runtime.h>

// Problem constants (fixed shapes from reference: B=16, H=W=1536)
#define H_DIM  1536
#define W_DIM  1536
#define B_DIM  16
#define HW     (H_DIM * W_DIM)      // 2359296
#define HW4    (HW / 4)             // 589824 float4 per plane
#define W4     (W_DIM / 4)          // 384 float4 per row

// 36-bit tile masks, bit index = (r%6)*6 + (c%6)
// R_POS = (0,4)(1,0)(1,2)(2,4)(3,1)(4,3)(4,5)(5,1) -> bits 4,6,8,16,19,27,29,31
// B_POS = (0,1)(1,3)(1,5)(2,1)(3,4)(4,0)(4,2)(5,4) -> bits 1,9,11,13,22,24,26,34
#define R_MASK ((1ull<<4)|(1ull<<6)|(1ull<<8)|(1ull<<16)|(1ull<<19)|(1ull<<27)|(1ull<<29)|(1ull<<31))
#define B_MASK ((1ull<<1)|(1ull<<9)|(1ull<<11)|(1ull<<13)|(1ull<<22)|(1ull<<24)|(1ull<<26)|(1ull<<34))

__global__ __launch_bounds__(W4, 4) void xflat_rgb_extract_kernel(
    const float4* __restrict__ green,   // [B,1,H,W]
    const float4* __restrict__ xtrans,  // [B,3,H,W]
    const float4* __restrict__ chroma,  // [B,2,H,W]
    float4* __restrict__ out)           // [B,3,H,W]
{
    const int w4 = threadIdx.x;        // 0..383
    const int h  = blockIdx.x;         // 0..1535
    const int b  = blockIdx.y;         // 0..15

    // Row mask patterns: 6 bits, doubled to 12 so lanes c0..c0+3 index directly
    const int r6 = h % 6;
    unsigned rrow = (unsigned)((R_MASK >> (r6 * 6)) & 63u);
    unsigned brow = (unsigned)((B_MASK >> (r6 * 6)) & 63u);
    rrow |= rrow << 6;
    brow |= brow << 6;

    const int c0 = (w4 * 4) % 6;       // column residue of lane 0

    // float4-unit offsets
    const int rowOff = h * W4 + w4;
    const int b1 = b * HW4;            // green plane base
    const int b2 = b * (2 * HW4);      // chroma base
    const int b3 = b * (3 * HW4);      // xtrans / out base

    // 5 independent 128-bit loads (MLP=5) — per-warp request depth is what
    // sustains 7.0+ TB/s through DRAM turnaround windows (R15 proved this:
    // splitting planes across CTAs dropped BW to 6.4 TB/s).
    const float4 xv0 = xtrans[b3 + rowOff];
    const float4 xv2 = xtrans[b3 + 2 * HW4 + rowOff];
    const float4 cv0 = chroma[b2 + rowOff];
    const float4 cv1 = chroma[b2 + HW4 + rowOff];
    const float4 gv  = green [b1 + rowOff];

    float4 o0, o2;
    o0.x = ((rrow >> (c0 + 0)) & 1u) ? xv0.x : cv0.x;
    o0.y = ((rrow >> (c0 + 1)) & 1u) ? xv0.y : cv0.y;
    o0.z = ((rrow >> (c0 + 2)) & 1u) ? xv0.z : cv0.z;
    o0.w = ((rrow >> (c0 + 3)) & 1u) ? xv0.w : cv0.w;

    o2.x = ((brow >> (c0 + 0)) & 1u) ? xv2.x : cv1.x;
    o2.y = ((brow >> (c0 + 1)) & 1u) ? xv2.y : cv1.y;
    o2.z = ((brow >> (c0 + 2)) & 1u) ? xv2.z : cv1.z;
    o2.w = ((brow >> (c0 + 3)) & 1u) ? xv2.w : cv1.w;

    out[b3 + rowOff]           = o0;
    out[b3 + HW4 + rowOff]     = gv;
    out[b3 + 2 * HW4 + rowOff] = o2;
}

extern "C" void kernel_launch(void* const* d_in, const int* in_sizes, int n_in,
                              void* d_out, int out_size)
{
    const float4* green  = (const float4*)d_in[0];  // green_pred  [16,1,1536,1536]
    const float4* xtrans = (const float4*)d_in[1];  // xtrans      [16,3,1536,1536]
    const float4* chroma = (const float4*)d_in[2];  // chroma_pred [16,2,1536,1536]
    float4* out = (float4*)d_out;                   // [16,3,1536,1536] float32

    dim3 grid(H_DIM, B_DIM);
    dim3 block(W4);
    xflat_rgb_extract_kernel<<<grid, block>>>(green, xtrans, chroma, out);
}

// round 17
// speedup vs baseline: 1.0386x; 1.0004x over previous
#include <cuda_runtime.h>

// Problem constants (fixed shapes from reference: B=16, H=W=1536)
#define H_DIM  1536
#define W_DIM  1536
#define B_DIM  16
#define HW     (H_DIM * W_DIM)      // 2359296
#define HW4    (HW / 4)             // 589824 float4 per plane
#define W4     (W_DIM / 4)          // 384 float4 per row

// 36-bit tile masks, bit index = (r%6)*6 + (c%6)
// R_POS = (0,4)(1,0)(1,2)(2,4)(3,1)(4,3)(4,5)(5,1) -> bits 4,6,8,16,19,27,29,31
// B_POS = (0,1)(1,3)(1,5)(2,1)(3,4)(4,0)(4,2)(5,4) -> bits 1,9,11,13,22,24,26,34
#define R_MASK ((1ull<<4)|(1ull<<6)|(1ull<<8)|(1ull<<16)|(1ull<<19)|(1ull<<27)|(1ull<<29)|(1ull<<31))
#define B_MASK ((1ull<<1)|(1ull<<9)|(1ull<<11)|(1ull<<13)|(1ull<<22)|(1ull<<24)|(1ull<<26)|(1ull<<34))

__global__ __launch_bounds__(W4, 4) void xflat_rgb_extract_kernel(
    const float4* __restrict__ green,   // [B,1,H,W]
    const float4* __restrict__ xtrans,  // [B,3,H,W]
    const float4* __restrict__ chroma,  // [B,2,H,W]
    float4* __restrict__ out)           // [B,3,H,W]
{
    const int w4 = threadIdx.x;        // 0..383
    const int h  = blockIdx.x;         // 0..1535
    const int b  = blockIdx.y;         // 0..15

    // Row mask patterns: 6 bits, doubled to 12 so lanes c0..c0+3 index directly
    const int r6 = h % 6;
    unsigned rrow = (unsigned)((R_MASK >> (r6 * 6)) & 63u);
    unsigned brow = (unsigned)((B_MASK >> (r6 * 6)) & 63u);
    rrow |= rrow << 6;
    brow |= brow << 6;

    const int c0 = (w4 * 4) % 6;       // column residue of lane 0

    // float4-unit offsets
    const int rowOff = h * W4 + w4;
    const int b1 = b * HW4;            // green plane base
    const int b2 = b * (2 * HW4);      // chroma base
    const int b3 = b * (3 * HW4);      // xtrans / out base

    // 5 independent 128-bit loads (MLP=5) — per-warp request depth across all
    // read streams is what sustains 7.0+ TB/s through DRAM turnaround windows
    // (R15: plane-split CTAs with MLP 1-2 dropped chip BW to 6.4 TB/s).
    const float4 xv0 = xtrans[b3 + rowOff];
    const float4 xv2 = xtrans[b3 + 2 * HW4 + rowOff];
    const float4 cv0 = chroma[b2 + rowOff];
    const float4 cv1 = chroma[b2 + HW4 + rowOff];
    const float4 gv  = green [b1 + rowOff];

    float4 o0, o2;
    o0.x = ((rrow >> (c0 + 0)) & 1u) ? xv0.x : cv0.x;
    o0.y = ((rrow >> (c0 + 1)) & 1u) ? xv0.y : cv0.y;
    o0.z = ((rrow >> (c0 + 2)) & 1u) ? xv0.z : cv0.z;
    o0.w = ((rrow >> (c0 + 3)) & 1u) ? xv0.w : cv0.w;

    o2.x = ((brow >> (c0 + 0)) & 1u) ? xv2.x : cv1.x;
    o2.y = ((brow >> (c0 + 1)) & 1u) ? xv2.y : cv1.y;
    o2.z = ((brow >> (c0 + 2)) & 1u) ? xv2.z : cv1.z;
    o2.w = ((brow >> (c0 + 3)) & 1u) ? xv2.w : cv1.w;

    out[b3 + rowOff]           = o0;
    out[b3 + HW4 + rowOff]     = gv;
    out[b3 + 2 * HW4 + rowOff] = o2;
}

extern "C" void kernel_launch(void* const* d_in, const int* in_sizes, int n_in,
                              void* d_out, int out_size)
{
    const float4* green  = (const float4*)d_in[0];  // green_pred  [16,1,1536,1536]
    const float4* xtrans = (const float4*)d_in[1];  // xtrans      [16,3,1536,1536]
    const float4* chroma = (const float4*)d_in[2];  // chroma_pred [16,2,1536,1536]
    float4* out = (float4*)d_out;                   // [16,3,1536,1536] float32

    dim3 grid(H_DIM, B_DIM);
    dim3 block(W4);
    xflat_rgb_extract_kernel<<<grid, block>>>(green, xtrans, chroma, out);
}